// round 15
// baseline (speedup 1.0000x reference)
#include <cuda_runtime.h>

// Equivariant linear: RS = [(16,0),(16,1),(16,2)], dim = 144, BATCH = 262144.
// Block-diagonal per (l,m): out[z,l,v,t] = sum_u Wl[v,u] * x[z,l,u,t],
// Wl[v,u] = weight[l*256 + v*16 + u] * 0.25 / sqrt(2l+1).
// Row layout: l=0 cols [0,16) d=1; l=1 idx 16+u*3+t; l=2 idx 64+u*5+t.
//
// R15: 288 threads = 9 warps = 9 slices (perfect balance, templated), 4-plane
// deinterleaved smem (conflict-free everywhere), LDG.128/STG.128 global I/O,
// W on the constant port, f32x2 FMAs. ~5 CTAs/SM (reg-limited) = 45 warps.

#define ROWS 32
#define PLANE 1184      // 32 * 37 floats per plane
#define NT 288          // 9 warps; warp id == slice id
#define DIM 144
#define EPT 4           // 1152 float4 / 288 threads

typedef unsigned long long ull;

__constant__ __align__(16) float cW[768];   // raw weights, W[l][v][u]

__device__ __forceinline__ ull pack_dup(float x) {
    ull r;
    asm("mov.b64 %0, {%1, %1};" : "=l"(r) : "f"(x));
    return r;
}
__device__ __forceinline__ ull pack2(float lo, float hi) {
    ull r;
    asm("mov.b64 %0, {%1, %2};" : "=l"(r) : "f"(lo), "f"(hi));
    return r;
}
__device__ __forceinline__ ull mul2(ull a, ull b) {
    ull r;
    asm("mul.rn.f32x2 %0, %1, %2;" : "=l"(r) : "l"(a), "l"(b));
    return r;
}
__device__ __forceinline__ void ffma2(ull& acc, ull w2, ull x2) {
    asm("fma.rn.f32x2 %0, %1, %2, %0;" : "+l"(acc) : "l"(w2), "l"(x2));
}
__device__ __forceinline__ float hadd2(ull p) {
    float lo, hi;
    asm("mov.b64 {%0, %1}, %2;" : "=f"(lo), "=f"(hi) : "l"(p));
    return lo + hi;
}

// Fully constant-folded slice: S compile-time -> every smem/const address is
// base + immediate; scale folded at compile time.
template<int S>
__device__ __forceinline__ void do_slice(float* __restrict__ sD, int base) {
    constexpr int l   = (S == 0) ? 0 : (S < 4) ? 1 : 2;
    constexpr int off = (S == 0) ? 0 : (S < 4) ? 16 + (S - 1) : 64 + (S - 4);
    constexpr int d   = (l == 0) ? 1 : (l == 1) ? 3 : 5;
    constexpr float scale =
        (l == 0) ? 0.25f
      : (l == 1) ? 0.25f * 0.57735026918962576f    // 1/sqrt(3)
                 : 0.25f * 0.44721359549995794f;   // 1/sqrt(5)

    const ull sc2 = pack_dup(scale);

    // Gather 16 inputs from planes (immediate offsets), pack u-pairs, scale.
    ull xr[8];
    #pragma unroll
    for (int up = 0; up < 8; up++) {
        int i0 = off + (2 * up) * d;       // folds to constant after unroll
        int i1 = i0 + d;
        float lo = sD[(i0 & 3) * PLANE + (i0 >> 2) + base];
        float hi = sD[(i1 & 3) * PLANE + (i1 >> 2) + base];
        xr[up] = mul2(pack2(lo, hi), sc2);
    }

    // v-outer matvec; warp-uniform LDC.128 x4 on the constant port.
    const ulonglong2* __restrict__ w2 =
        reinterpret_cast<const ulonglong2*>(cW + l * 256);
    #pragma unroll
    for (int v = 0; v < 16; v++) {
        ulonglong2 wa = w2[v * 4 + 0];
        ulonglong2 wb = w2[v * 4 + 1];
        ulonglong2 wc = w2[v * 4 + 2];
        ulonglong2 wd = w2[v * 4 + 3];

        ull a = 0ull;
        ffma2(a, wa.x, xr[0]);
        ffma2(a, wa.y, xr[1]);
        ffma2(a, wb.x, xr[2]);
        ffma2(a, wb.y, xr[3]);
        ffma2(a, wc.x, xr[4]);
        ffma2(a, wc.y, xr[5]);
        ffma2(a, wd.x, xr[6]);
        ffma2(a, wd.y, xr[7]);

        int iv = off + v * d;              // folds to constant
        sD[(iv & 3) * PLANE + (iv >> 2) + base] = hadd2(a);
    }
}

__global__ __launch_bounds__(NT) void eq_linear_kernel(
    const float* __restrict__ x,
    float* __restrict__ y)
{
    __shared__ float sD[4 * PLANE];

    const int tid  = threadIdx.x;
    const int lane = tid & 31;
    const int wrp  = tid >> 5;      // 0..8 == slice id

    const long long row0 = (long long)blockIdx.x * ROWS;

    // Load: LDG.128 coalesced, deinterleave into 4 planes (scalar STS at
    // lane-consecutive addresses -> 1 wf). Plane addr a = i + i/36.
    // 288 = 8*36 -> stepping i += 288 gives q += 8 exactly (no carry).
    {
        const float4* __restrict__ gsrc =
            reinterpret_cast<const float4*>(x) + row0 * 36;
        int q = tid / 36;
        int i = tid;
        #pragma unroll
        for (int k = 0; k < EPT; k++) {
            float4 v = gsrc[i];
            int a = i + q;                 // == r*37 + c4
            sD[a]             = v.x;
            sD[a + PLANE]     = v.y;
            sD[a + 2 * PLANE] = v.z;
            sD[a + 3 * PLANE] = v.w;
            i += NT; q += 8;
        }
    }
    __syncthreads();

    // Compute: warp == slice, perfectly balanced; lane = row.
    {
        const int base = lane * 37;
        switch (wrp) {
            case 0: do_slice<0>(sD, base); break;
            case 1: do_slice<1>(sD, base); break;
            case 2: do_slice<2>(sD, base); break;
            case 3: do_slice<3>(sD, base); break;
            case 4: do_slice<4>(sD, base); break;
            case 5: do_slice<5>(sD, base); break;
            case 6: do_slice<6>(sD, base); break;
            case 7: do_slice<7>(sD, base); break;
            default: do_slice<8>(sD, base); break;
        }
    }
    __syncthreads();

    // Store: re-interleave from planes (conflict-free LDS), STG.128.
    {
        float4* __restrict__ gdst =
            reinterpret_cast<float4*>(y) + row0 * 36;
        int q = tid / 36;
        int i = tid;
        #pragma unroll
        for (int k = 0; k < EPT; k++) {
            int a = i + q;
            float4 v;
            v.x = sD[a];
            v.y = sD[a + PLANE];
            v.z = sD[a + 2 * PLANE];
            v.w = sD[a + 3 * PLANE];
            gdst[i] = v;
            i += NT; q += 8;
        }
    }
}

extern "C" void kernel_launch(void* const* d_in, const int* in_sizes, int n_in,
                              void* d_out, int out_size)
{
    const float* feat = (const float*)d_in[0];
    const float* w    = (const float*)d_in[1];
    float* out        = (float*)d_out;

    // Raw weights -> constant bank (D2D async memcpy node; graph-capturable).
    cudaMemcpyToSymbolAsync(cW, w, 768 * sizeof(float), 0,
                            cudaMemcpyDeviceToDevice, 0);

    const int batch  = in_sizes[0] / DIM;   // 262144
    const int blocks = batch / ROWS;        // 8192

    eq_linear_kernel<<<blocks, NT>>>(feat, out);
}

// round 16
// speedup vs baseline: 1.0712x; 1.0712x over previous
#include <cuda_runtime.h>

// Equivariant linear: RS = [(16,0),(16,1),(16,2)], dim = 144, BATCH = 262144.
// Block-diagonal per (l,m): out[z,l,v,t] = sum_u Wl[v,u] * x[z,l,u,t],
// Wl[v,u] = weight[l*256 + v*16 + u] * 0.25 / sqrt(2l+1).
// Row layout: l=0 cols [0,16) d=1; l=1 idx 16+u*3+t; l=2 idx 64+u*5+t.
//
// R16: persistent CTAs (592 = 148 SMs x 4) with distance-1 register
// prefetch: LDG.128 for tile t+stride issues right after STS of tile t,
// hiding DRAM latency behind compute+store. 9 warps = 9 templated slices
// (balanced), 4-plane conflict-free smem, W on the constant port, f32x2.

#define ROWS 32
#define PLANE 1184      // 32 * 37 floats per plane
#define NT 288          // 9 warps; warp id == slice id
#define DIM 144
#define EPT 4           // 1152 float4 / 288 threads
#define NTILES 8192     // 262144 / 32
#define NBLOCKS 592     // 148 * 4

typedef unsigned long long ull;

__constant__ __align__(16) float cW[768];   // raw weights, W[l][v][u]

__device__ __forceinline__ ull pack_dup(float x) {
    ull r;
    asm("mov.b64 %0, {%1, %1};" : "=l"(r) : "f"(x));
    return r;
}
__device__ __forceinline__ ull pack2(float lo, float hi) {
    ull r;
    asm("mov.b64 %0, {%1, %2};" : "=l"(r) : "f"(lo), "f"(hi));
    return r;
}
__device__ __forceinline__ ull mul2(ull a, ull b) {
    ull r;
    asm("mul.rn.f32x2 %0, %1, %2;" : "=l"(r) : "l"(a), "l"(b));
    return r;
}
__device__ __forceinline__ void ffma2(ull& acc, ull w2, ull x2) {
    asm("fma.rn.f32x2 %0, %1, %2, %0;" : "+l"(acc) : "l"(w2), "l"(x2));
}
__device__ __forceinline__ float hadd2(ull p) {
    float lo, hi;
    asm("mov.b64 {%0, %1}, %2;" : "=f"(lo), "=f"(hi) : "l"(p));
    return lo + hi;
}

// Fully constant-folded slice: S compile-time -> every smem/const address is
// base + immediate; scale folded at compile time.
template<int S>
__device__ __forceinline__ void do_slice(float* __restrict__ sD, int base) {
    constexpr int l   = (S == 0) ? 0 : (S < 4) ? 1 : 2;
    constexpr int off = (S == 0) ? 0 : (S < 4) ? 16 + (S - 1) : 64 + (S - 4);
    constexpr int d   = (l == 0) ? 1 : (l == 1) ? 3 : 5;
    constexpr float scale =
        (l == 0) ? 0.25f
      : (l == 1) ? 0.25f * 0.57735026918962576f    // 1/sqrt(3)
                 : 0.25f * 0.44721359549995794f;   // 1/sqrt(5)

    const ull sc2 = pack_dup(scale);

    ull xr[8];
    #pragma unroll
    for (int up = 0; up < 8; up++) {
        int i0 = off + (2 * up) * d;       // folds to constant after unroll
        int i1 = i0 + d;
        float lo = sD[(i0 & 3) * PLANE + (i0 >> 2) + base];
        float hi = sD[(i1 & 3) * PLANE + (i1 >> 2) + base];
        xr[up] = mul2(pack2(lo, hi), sc2);
    }

    const ulonglong2* __restrict__ w2 =
        reinterpret_cast<const ulonglong2*>(cW + l * 256);
    #pragma unroll
    for (int v = 0; v < 16; v++) {
        ulonglong2 wa = w2[v * 4 + 0];
        ulonglong2 wb = w2[v * 4 + 1];
        ulonglong2 wc = w2[v * 4 + 2];
        ulonglong2 wd = w2[v * 4 + 3];

        ull a = 0ull;
        ffma2(a, wa.x, xr[0]);
        ffma2(a, wa.y, xr[1]);
        ffma2(a, wb.x, xr[2]);
        ffma2(a, wb.y, xr[3]);
        ffma2(a, wc.x, xr[4]);
        ffma2(a, wc.y, xr[5]);
        ffma2(a, wd.x, xr[6]);
        ffma2(a, wd.y, xr[7]);

        int iv = off + v * d;              // folds to constant
        sD[(iv & 3) * PLANE + (iv >> 2) + base] = hadd2(a);
    }
}

__global__ __launch_bounds__(NT) void eq_linear_kernel(
    const float* __restrict__ x,
    float* __restrict__ y)
{
    __shared__ float sD[4 * PLANE];

    const int tid  = threadIdx.x;
    const int lane = tid & 31;
    const int wrp  = tid >> 5;      // 0..8 == slice id
    const int base = lane * 37;

    // Staging addresses: element i_k = tid + 288k of the tile; plane address
    // a_k = i_k + i_k/36 = (tid + tid/36) + 296k  (288 = 8*36, exact).
    const int a0 = tid + tid / 36;

    const float4* __restrict__ x4 = reinterpret_cast<const float4*>(x);
    float4*       __restrict__ y4 = reinterpret_cast<float4*>(y);

    // Prologue: prefetch first tile into registers.
    float4 buf[EPT];
    {
        const float4* __restrict__ g = x4 + (long long)blockIdx.x * ROWS * 36;
        #pragma unroll
        for (int k = 0; k < EPT; k++) buf[k] = g[tid + k * NT];
    }

    for (int t = blockIdx.x; t < NTILES; t += NBLOCKS) {
        // Wait until previous tile's store phase finished reading the planes.
        __syncthreads();

        // Deinterleave buffered tile into planes (scalar STS, 1 wf each).
        #pragma unroll
        for (int k = 0; k < EPT; k++) {
            int a = a0 + k * (NT + 8);
            sD[a]             = buf[k].x;
            sD[a + PLANE]     = buf[k].y;
            sD[a + 2 * PLANE] = buf[k].z;
            sD[a + 3 * PLANE] = buf[k].w;
        }

        // Prefetch next tile now; latency hides behind compute + store.
        const int tn = t + NBLOCKS;
        if (tn < NTILES) {
            const float4* __restrict__ g = x4 + (long long)tn * ROWS * 36;
            #pragma unroll
            for (int k = 0; k < EPT; k++) buf[k] = g[tid + k * NT];
        }
        __syncthreads();

        // Compute: warp == slice, perfectly balanced; lane = row.
        switch (wrp) {
            case 0: do_slice<0>(sD, base); break;
            case 1: do_slice<1>(sD, base); break;
            case 2: do_slice<2>(sD, base); break;
            case 3: do_slice<3>(sD, base); break;
            case 4: do_slice<4>(sD, base); break;
            case 5: do_slice<5>(sD, base); break;
            case 6: do_slice<6>(sD, base); break;
            case 7: do_slice<7>(sD, base); break;
            default: do_slice<8>(sD, base); break;
        }
        __syncthreads();

        // Store: re-interleave from planes (conflict-free LDS), STG.128.
        {
            float4* __restrict__ g = y4 + (long long)t * ROWS * 36;
            #pragma unroll
            for (int k = 0; k < EPT; k++) {
                int a = a0 + k * (NT + 8);
                float4 v;
                v.x = sD[a];
                v.y = sD[a + PLANE];
                v.z = sD[a + 2 * PLANE];
                v.w = sD[a + 3 * PLANE];
                g[tid + k * NT] = v;
            }
        }
    }
}

extern "C" void kernel_launch(void* const* d_in, const int* in_sizes, int n_in,
                              void* d_out, int out_size)
{
    const float* feat = (const float*)d_in[0];
    const float* w    = (const float*)d_in[1];
    float* out        = (float*)d_out;

    // Raw weights -> constant bank (D2D async memcpy node; graph-capturable).
    cudaMemcpyToSymbolAsync(cW, w, 768 * sizeof(float), 0,
                            cudaMemcpyDeviceToDevice, 0);

    eq_linear_kernel<<<NBLOCKS, NT>>>(feat, out);
}